// round 5
// baseline (speedup 1.0000x reference)
#include <cuda_runtime.h>
#include <stdint.h>

// SpikeFP32Embedding: out[t, :, :] = weight_pulse[token_ids[t], :, :]
// token_ids: [16384] int32; weight_pulse: [32768, 128, 32] f32; out: [16384, 128, 32] f32
// Row = 4096 f32 = 1024 float4 = 16 KB.
//
// Persistent, software-pipelined gather: each CTA strides over tokens,
// double-buffering row data in registers and prefetching the next token id,
// so row loads for token t+1 are in flight while token t's stores drain.
// Default L2 policy for reads (R4 showed evict_last thrashes); streaming
// evict-first stores keep the 256MB write stream out of L2.

static constexpr int ROW_FLOAT4 = 1024;   // float4 per row
static constexpr int THREADS    = 256;
static constexpr int PER_THREAD = ROW_FLOAT4 / THREADS;  // 4
static constexpr int GRID       = 592;    // 4 CTAs/SM * 148 SMs

__global__ __launch_bounds__(THREADS)
void spike_embed_gather(const int* __restrict__ tok,
                        const float4* __restrict__ pulse,
                        float4* __restrict__ out,
                        int n)
{
    const int stride = gridDim.x;
    int t = blockIdx.x;
    if (t >= n) return;

    // Prologue: loads for first token, prefetch id of the second.
    int row = __ldg(tok + t);
    float4 buf[PER_THREAD];
    {
        const float4* __restrict__ src = pulse + (size_t)row * ROW_FLOAT4 + threadIdx.x;
#pragma unroll
        for (int i = 0; i < PER_THREAD; ++i)
            buf[i] = __ldg(src + i * THREADS);
    }
    int t_next = t + stride;
    int row_next = (t_next < n) ? __ldg(tok + t_next) : 0;

    while (true) {
        // Issue next row's loads first (keeps read stream continuous).
        float4 buf2[PER_THREAD];
        const bool have_next = (t_next < n);
        if (have_next) {
            const float4* __restrict__ src2 =
                pulse + (size_t)row_next * ROW_FLOAT4 + threadIdx.x;
#pragma unroll
            for (int i = 0; i < PER_THREAD; ++i)
                buf2[i] = __ldg(src2 + i * THREADS);
        }

        // Prefetch the id two iterations ahead (hides id-load latency).
        const int t_next2 = t_next + stride;
        const int row_next2 = (have_next && t_next2 < n) ? __ldg(tok + t_next2) : 0;

        // Store current token's row (posted, evict-first).
        float4* __restrict__ dst = out + (size_t)t * ROW_FLOAT4 + threadIdx.x;
#pragma unroll
        for (int i = 0; i < PER_THREAD; ++i)
            __stcs(dst + i * THREADS, buf[i]);

        if (!have_next) break;

#pragma unroll
        for (int i = 0; i < PER_THREAD; ++i)
            buf[i] = buf2[i];
        t = t_next;
        t_next = t_next2;
        row_next = row_next2;
    }
}

extern "C" void kernel_launch(void* const* d_in, const int* in_sizes, int n_in,
                              void* d_out, int out_size)
{
    const int*    tok   = (const int*)d_in[0];      // [16384]
    const float4* pulse = (const float4*)d_in[1];   // [32768*1024] float4
    float4*       out   = (float4*)d_out;

    const int n_tokens = in_sizes[0];               // 16384
    spike_embed_gather<<<GRID, THREADS>>>(tok, pulse, out, n_tokens);
}

// round 6
// speedup vs baseline: 1.0018x; 1.0018x over previous
#include <cuda_runtime.h>
#include <stdint.h>

// SpikeFP32Embedding: out[t, :, :] = weight_pulse[token_ids[t], :, :]
// token_ids: [16384] int32; weight_pulse: [32768, 4096] f32; out: [16384, 4096] f32
// Row = 16 KB contiguous.
//
// TMA bulk-copy pipeline: each CTA (1 warp) streams ~28 tokens through a
// 3-stage 16KB smem ring. 16KB G2S (mbarrier complete_tx) + 16KB S2G
// (bulk_group, L2 evict_first hint on writes). Goal: large contiguous DRAM
// bursts instead of 128B LDG/STG shreds -> higher DRAM utilization.

static constexpr int ROW_BYTES = 16384;
static constexpr int STAGES    = 3;
static constexpr int GRID      = 592;     // 4 CTAs/SM * 148 SMs, all resident
static constexpr int THREADS   = 32;
static constexpr int SMEM_BUF_OFF = 1024; // mbarriers live below
static constexpr int SMEM_TOTAL   = SMEM_BUF_OFF + STAGES * ROW_BYTES; // 50176

__device__ __forceinline__ uint32_t s2u(const void* p) {
    return (uint32_t)__cvta_generic_to_shared(p);
}

__device__ __forceinline__ void mbar_wait_parity(uint32_t mb, int parity) {
    asm volatile(
        "{\n\t"
        ".reg .pred P;\n\t"
        "WAIT_%=: \n\t"
        "mbarrier.try_wait.parity.acquire.cta.shared::cta.b64 P, [%0], %1, 0x989680;\n\t"
        "@!P bra WAIT_%=;\n\t"
        "}"
        :: "r"(mb), "r"((uint32_t)parity) : "memory");
}

__global__ __launch_bounds__(THREADS)
void spike_embed_tma(const int* __restrict__ tok,
                     const char* __restrict__ pulse,
                     char* __restrict__ out, int n)
{
    extern __shared__ char smem[];
    const uint32_t mbar0 = s2u(smem);
    const uint32_t buf0  = mbar0 + SMEM_BUF_OFF;
    const int lane = threadIdx.x;
    const int bid  = blockIdx.x;

    // Lane L preloads the id of this CTA's L-th token (cnt <= 28 < 32).
    const int t_lane  = bid + lane * GRID;
    const int id_lane = (t_lane < n) ? __ldg(tok + t_lane) : 0;
    const int cnt = (n > bid) ? ((n - bid + GRID - 1) / GRID) : 0;

    if (lane == 0) {
#pragma unroll
        for (int s = 0; s < STAGES; ++s)
            asm volatile("mbarrier.init.shared.b64 [%0], 1;"
                         :: "r"(mbar0 + 8u * s) : "memory");
        asm volatile("fence.proxy.async.shared::cta;" ::: "memory");
    }
    __syncwarp();

    unsigned long long pol;   // evict-first policy for the 256MB write stream
    asm("createpolicy.fractional.L2::evict_first.b64 %0, 1.0;" : "=l"(pol));

    // Prologue: fill all stages.
#pragma unroll
    for (int s = 0; s < STAGES; ++s) {
        const int row = __shfl_sync(0xffffffffu, id_lane, s);
        if (lane == 0 && s < cnt) {
            const uint32_t mb = mbar0 + 8u * s;
            asm volatile("mbarrier.arrive.expect_tx.shared.b64 _, [%0], %1;"
                         :: "r"(mb), "r"((uint32_t)ROW_BYTES) : "memory");
            asm volatile(
                "cp.async.bulk.shared::cta.global.mbarrier::complete_tx::bytes "
                "[%0], [%1], %2, [%3];"
                :: "r"(buf0 + (uint32_t)s * ROW_BYTES),
                   "l"(pulse + (size_t)row * ROW_BYTES),
                   "r"((uint32_t)ROW_BYTES), "r"(mb) : "memory");
        }
    }

    for (int k = 0; k < cnt; ++k) {
        const int s   = k % STAGES;
        const int par = (k / STAGES) & 1;

        if (lane == 0) {
            mbar_wait_parity(mbar0 + 8u * s, par);
            // Store token k's row (bulk S2G, evict-first in L2).
            asm volatile(
                "cp.async.bulk.global.shared::cta.bulk_group.L2::cache_hint "
                "[%0], [%1], %2, %3;"
                :: "l"(out + (size_t)(bid + (size_t)k * GRID) * ROW_BYTES),
                   "r"(buf0 + (uint32_t)s * ROW_BYTES),
                   "r"((uint32_t)ROW_BYTES), "l"(pol) : "memory");
            asm volatile("cp.async.bulk.commit_group;" ::: "memory");
        }

        // Refill the stage consumed LAST iteration (group k-1 must be read-done;
        // wait_group.read 1 after committing group k guarantees it).
        const int j = k - 1 + STAGES;                 // token for stage (k-1)%STAGES
        const int row_j = __shfl_sync(0xffffffffu, id_lane, j & 31);
        if (lane == 0 && k >= 1 && j < cnt) {
            asm volatile("cp.async.bulk.wait_group.read 1;" ::: "memory");
            const int sr = (k - 1) % STAGES;
            const uint32_t mb = mbar0 + 8u * sr;
            asm volatile("mbarrier.arrive.expect_tx.shared.b64 _, [%0], %1;"
                         :: "r"(mb), "r"((uint32_t)ROW_BYTES) : "memory");
            asm volatile(
                "cp.async.bulk.shared::cta.global.mbarrier::complete_tx::bytes "
                "[%0], [%1], %2, [%3];"
                :: "r"(buf0 + (uint32_t)sr * ROW_BYTES),
                   "l"(pulse + (size_t)row_j * ROW_BYTES),
                   "r"((uint32_t)ROW_BYTES), "r"(mb) : "memory");
        }
    }

    if (lane == 0)
        asm volatile("cp.async.bulk.wait_group 0;" ::: "memory");
}

extern "C" void kernel_launch(void* const* d_in, const int* in_sizes, int n_in,
                              void* d_out, int out_size)
{
    const int*  tok   = (const int*)d_in[0];     // [16384]
    const char* pulse = (const char*)d_in[1];    // [32768 * 16384] bytes
    char*       out   = (char*)d_out;

    const int n_tokens = in_sizes[0];            // 16384

    static bool attr_set = false;
    if (!attr_set) {
        cudaFuncSetAttribute(spike_embed_tma,
                             cudaFuncAttributeMaxDynamicSharedMemorySize,
                             SMEM_TOTAL);
        attr_set = true;
    }
    spike_embed_tma<<<GRID, THREADS, SMEM_TOTAL>>>(tok, pulse, out, n_tokens);
}

// round 7
// speedup vs baseline: 1.0840x; 1.0820x over previous
#include <cuda_runtime.h>
#include <stdint.h>

// SpikeFP32Embedding: out[t, :, :] = weight_pulse[token_ids[t], :, :]
// token_ids: [16384] int32; weight_pulse: [32768, 128, 32] f32; out: [16384, 128, 32] f32
// Row = 4096 f32 = 1024 float4 = 16 KB.
//
// R1 gather + 2 tokens per CTA: both token ids load back-to-back (one latency
// exposure), all 8 row loads batched (MLP 8/thread), then 8 streaming stores.
// Default L2 policy on reads (evict_last thrashes, R4); evict-first stores.

static constexpr int ROW_FLOAT4 = 1024;   // float4 per row
static constexpr int THREADS    = 256;
static constexpr int PER_THREAD = ROW_FLOAT4 / THREADS;  // 4
static constexpr int TOK_PER_CTA = 2;

__global__ __launch_bounds__(THREADS)
void spike_embed_gather(const int* __restrict__ tok,
                        const float4* __restrict__ pulse,
                        float4* __restrict__ out,
                        int n)
{
    const int t0 = blockIdx.x * TOK_PER_CTA;
    const int t1 = t0 + 1;

    // Both id loads issue back-to-back: one latency exposure for the pair.
    const int row0 = __ldg(tok + t0);
    const int row1 = (t1 < n) ? __ldg(tok + t1) : row0;

    const float4* __restrict__ src0 = pulse + (size_t)row0 * ROW_FLOAT4 + threadIdx.x;
    const float4* __restrict__ src1 = pulse + (size_t)row1 * ROW_FLOAT4 + threadIdx.x;

    float4 v0[PER_THREAD], v1[PER_THREAD];
#pragma unroll
    for (int i = 0; i < PER_THREAD; ++i)
        v0[i] = __ldg(src0 + i * THREADS);
#pragma unroll
    for (int i = 0; i < PER_THREAD; ++i)
        v1[i] = __ldg(src1 + i * THREADS);

    float4* __restrict__ dst0 = out + (size_t)t0 * ROW_FLOAT4 + threadIdx.x;
#pragma unroll
    for (int i = 0; i < PER_THREAD; ++i)
        __stcs(dst0 + i * THREADS, v0[i]);

    if (t1 < n) {
        float4* __restrict__ dst1 = out + (size_t)t1 * ROW_FLOAT4 + threadIdx.x;
#pragma unroll
        for (int i = 0; i < PER_THREAD; ++i)
            __stcs(dst1 + i * THREADS, v1[i]);
    }
}

extern "C" void kernel_launch(void* const* d_in, const int* in_sizes, int n_in,
                              void* d_out, int out_size)
{
    const int*    tok   = (const int*)d_in[0];      // [16384]
    const float4* pulse = (const float4*)d_in[1];   // [32768*1024] float4
    float4*       out   = (float4*)d_out;

    const int n_tokens = in_sizes[0];               // 16384
    const int grid = (n_tokens + TOK_PER_CTA - 1) / TOK_PER_CTA;
    spike_embed_gather<<<grid, THREADS>>>(tok, pulse, out, n_tokens);
}

// round 8
// speedup vs baseline: 1.0912x; 1.0067x over previous
#include <cuda_runtime.h>
#include <stdint.h>

// SpikeFP32Embedding: out[t, :, :] = weight_pulse[token_ids[t], :, :]
// token_ids: [8*2048] int32; weight_pulse: [32768, 128, 32] f32; out: [16384, 128, 32] f32
// Row = 128*32 floats = 4096 f32 = 1024 float4 = 16 KB.
//
// Converged optimum (R1 config). One CTA per token, 256 threads, 4 float4
// loads batched then 4 streaming stores. Measured 6.15 TB/s HBM (77.5% DRAM
// active) — at the r/w-mix DRAM ceiling; sort, evict-policy hints, persistent
// pipelining, TMA bulk copy, and multi-token CTAs all measured equal or worse.

static constexpr int ROW_FLOAT4 = 1024;   // float4 per row
static constexpr int THREADS    = 256;
static constexpr int PER_THREAD = ROW_FLOAT4 / THREADS;  // 4

__global__ __launch_bounds__(THREADS, 8)
void spike_embed_gather(const int* __restrict__ tok,
                        const float4* __restrict__ pulse,
                        float4* __restrict__ out)
{
    const int t = blockIdx.x;
    const int row = __ldg(tok + t);

    const float4* __restrict__ src = pulse + (size_t)row * ROW_FLOAT4 + threadIdx.x;
    float4* __restrict__ dst = out + (size_t)t * ROW_FLOAT4 + threadIdx.x;

    float4 v[PER_THREAD];
#pragma unroll
    for (int i = 0; i < PER_THREAD; ++i)
        v[i] = __ldg(src + i * THREADS);

#pragma unroll
    for (int i = 0; i < PER_THREAD; ++i)
        __stcs(dst + i * THREADS, v[i]);
}

extern "C" void kernel_launch(void* const* d_in, const int* in_sizes, int n_in,
                              void* d_out, int out_size)
{
    const int*    tok   = (const int*)d_in[0];       // [16384]
    const float4* pulse = (const float4*)d_in[1];    // [32768*1024] float4
    float4*       out   = (float4*)d_out;

    const int n_tokens = in_sizes[0];                // 16384
    spike_embed_gather<<<n_tokens, THREADS>>>(tok, pulse, out);
}